// round 15
// baseline (speedup 1.0000x reference)
#include <cuda_runtime.h>

// ---------------------------------------------------------------------------
// QHashSoftmax: LUT fixed-point softmax, exact-integer reformulation.
//   idx = clamp(rne(x*16), -128, 127) & 255            (cvt.rni.sat.s8)
//   k[idx] = clip(rint(exp(signed(idx)/16 * scale)*128), 0, 127)   (u8 LUT)
//   S = sum(k) over 1024-element row   (exact integer, <= 130048)
//   t = min(floor(S/k), 1023)   (k=0 -> 1023)  [fp32 div+floor exact here]
//   out = min(rint(128/t), 127) / 128           (t=0 -> inf -> 127)
//
// Structure (R15 = R7 best-bench main kernel verbatim + fast setup):
//  - main: 4 rows / 256-thread block, thread t = float4 index t of each row
//    (rows at +256): every LDG/STG per-instruction fully coalesced;
//    byte-packed codes, dp4a partials, packed-pair REDUX (16-bit halves,
//    32-lane sums <= 16256, no carry), 4x32-bit smem atomics;
//    exp table u8[256] (gather conflict deg <= 2); ocode u8[128] = 32
//    words, one/bank -> conflict-FREE gather; .cs hints; lb(256,6).
//  - setup: fp32 expf with BOUNDARY-GUARDED fp64 fallback — fp64 exp only
//    when exp(val)*128 is within 1e-3 of a round-half-even boundary (2ulp
//    fp32 error ~8e-5 << 1e-3 guard), so the table is provably identical
//    to the all-fp64 build at ~1/5 the serial cost.
// ---------------------------------------------------------------------------

__device__ unsigned char g_exp_u8[256];   // wrapped-code -> k

__global__ void qhs_setup_kernel(const float* __restrict__ scale_ptr) {
    int i = threadIdx.x;                      // 0..255 = wrapped address
    float scale = *scale_ptr;
    int sv = (i >= 128) ? (i - 256) : i;      // two's-complement decode
    float val = (float)sv * 0.0625f * scale;  // fp32, matches reference

    // fast fp32 path; fp64 only when within guard of a rounding boundary
    float ef = expf(val);
    float scaled = ef * 128.0f;               // exact pow2 scaling
    float near = scaled - floorf(scaled);     // distance into [0,1)
    float dist = fabsf(near - 0.5f);          // to the rne decision point
    double r;
    if (dist < 1e-3f) {
        r = rint(exp((double)val) * 128.0);   // exact tie-break
    } else {
        r = (double)rintf(scaled);            // fp32 verdict is safe
    }
    if (r > 127.0) r = 127.0;
    if (r < 0.0)   r = 0.0;
    g_exp_u8[i] = (unsigned char)(int)r;
}

// clamp(round-half-even(f), -128, 127) & 255 in one convert + one mask
__device__ __forceinline__ unsigned qhs_code(float f) {
    int r;
    asm("cvt.rni.sat.s8.f32 %0, %1;" : "=r"(r) : "f"(f));
    return (unsigned)r & 255u;
}

#define ROWS_PER_BLOCK 4

__global__ __launch_bounds__(256, 6) void qhs_main_kernel(
    const float4* __restrict__ x, float4* __restrict__ out)
{
    __shared__ unsigned char sk8[256];                    // exp codes (u8)
    __shared__ unsigned char ocode[ROWS_PER_BLOCK][128];  // out codes by k
    __shared__ int sS[ROWS_PER_BLOCK];                    // row sums

    const int tid = threadIdx.x;

    sk8[tid] = g_exp_u8[tid];
    if (tid < ROWS_PER_BLOCK) sS[tid] = 0;

    // Coalesced: thread t -> float4 index t of each of the block's 4 rows.
    const long long base =
        (long long)blockIdx.x * (ROWS_PER_BLOCK * 256) + tid;

    float4 v0 = __ldcs(&x[base]);
    float4 v1 = __ldcs(&x[base + 256]);
    float4 v2 = __ldcs(&x[base + 512]);
    float4 v3 = __ldcs(&x[base + 768]);

    // Quantize to packed 8-bit codes (independent of tables).
    unsigned pidx[4];
#define QHS_PACK(j, v)                                                  \
    pidx[j] = qhs_code(v.x * 16.0f)          |                          \
              (qhs_code(v.y * 16.0f) << 8)   |                          \
              (qhs_code(v.z * 16.0f) << 16)  |                          \
              (qhs_code(v.w * 16.0f) << 24)
    QHS_PACK(0, v0); QHS_PACK(1, v1); QHS_PACK(2, v2); QHS_PACK(3, v3);
#undef QHS_PACK

    __syncthreads();   // sk8 + sS ready

    // ---- Phase 1: gather k bytes, pack, packed-pair redux ---------------
    unsigned pk[4];
    unsigned d[4];
#pragma unroll
    for (int j = 0; j < 4; j++) {
        unsigned p = pidx[j];
        unsigned k0 = sk8[p & 255u];
        unsigned k1 = sk8[(p >> 8) & 255u];
        unsigned k2 = sk8[(p >> 16) & 255u];
        unsigned k3 = sk8[p >> 24];
        pk[j] = k0 | (k1 << 8) | (k2 << 16) | (k3 << 24);
        d[j] = __dp4a(pk[j], 0x01010101u, 0u);     // <= 508
    }
    // rows (0,1) and (2,3) in 16-bit halves; 32-lane sum <= 16256 (no carry)
    unsigned s01 = __reduce_add_sync(0xFFFFFFFFu, d[0] | (d[1] << 16));
    unsigned s23 = __reduce_add_sync(0xFFFFFFFFu, d[2] | (d[3] << 16));
    if ((tid & 31) == 0) {
        atomicAdd(&sS[0], (int)(s01 & 0xFFFFu));
        atomicAdd(&sS[1], (int)(s01 >> 16));
        atomicAdd(&sS[2], (int)(s23 & 0xFFFFu));
        atomicAdd(&sS[3], (int)(s23 >> 16));
    }

    __syncthreads();   // all sums complete

    // ---- Phase 2: per-row output-code tables (indexed by k) -------------
    // 4 rows x 128 entries = 512; each thread builds 2.
#pragma unroll
    for (int e = tid; e < ROWS_PER_BLOCK * 128; e += 256) {
        int rw = e >> 7;
        int kk = e & 127;
        float Sf = (float)sS[rw];                      // exact (< 2^18)
        // floor(S/k): IEEE div then floor — exact (err < 1/k fractional gap).
        // kk==0 -> +inf -> clipped to 1023 (reference e==0 branch).
        float t = fminf(floorf(__fdiv_rn(Sf, (float)kk)), 1023.0f);
        // t==0 -> +inf -> clipped to 127 (reference 1/0 saturation).
        float code = fminf(rintf(__fdiv_rn(128.0f, t)), 127.0f);
        ocode[rw][kk] = (unsigned char)(int)code;
    }

    __syncthreads();   // tables ready

    // ---- Phase 3: conflict-free byte gathers + coalesced stores ---------
#pragma unroll
    for (int j = 0; j < 4; j++) {
        unsigned p = pk[j];
        float4 o;
        o.x = (float)ocode[j][p & 255u]         * 0.0078125f;
        o.y = (float)ocode[j][(p >> 8) & 255u]  * 0.0078125f;
        o.z = (float)ocode[j][(p >> 16) & 255u] * 0.0078125f;
        o.w = (float)ocode[j][p >> 24]          * 0.0078125f;
        __stcs(&out[base + j * 256], o);
    }
}

extern "C" void kernel_launch(void* const* d_in, const int* in_sizes, int n_in,
                              void* d_out, int out_size) {
    const float* x     = (const float*)d_in[0];   // [4,12,1024,1024] fp32
    const float* scale = (const float*)d_in[1];   // scalar fp32

    const int n_elems = in_sizes[0];
    const int n_rows  = n_elems >> 10;                   // rows of 1024
    const int n_blocks = n_rows / ROWS_PER_BLOCK;        // 12288

    qhs_setup_kernel<<<1, 256>>>(scale);
    qhs_main_kernel<<<n_blocks, 256>>>((const float4*)x, (float4*)d_out);
}

// round 16
// speedup vs baseline: 1.0276x; 1.0276x over previous
#include <cuda_runtime.h>

// ---------------------------------------------------------------------------
// QHashSoftmax: LUT fixed-point softmax, exact-integer reformulation.
//   idx = clamp(rne(x*16), -128, 127) & 255            (cvt.rni.sat.s8)
//   k[idx] = clip(rint(exp(signed(idx)/16 * scale)*128), 0, 127)   (u8 LUT)
//   S = sum(k) over 1024-element row   (exact integer, <= 130048)
//   t = min(floor(S/k), 1023)   (k=0 -> 1023)  [fp32 div+floor exact here]
//   out = min(rint(128/t), 127) / 128           (t=0 -> inf -> 127)
//
// Structure (R16 = R7 main kernel + FUSED table build, single launch):
//  - No setup kernel: each block computes the 256-entry exp table itself —
//    one expf per thread, issued while the block's 4 DRAM loads are in
//    flight (MUFU hidden under ~600cyc load latency). Boundary-guarded
//    fp64 exp fallback (dist<1e-3 to the rne boundary; fp32 err ~8e-5)
//    keeps the table bit-identical to an all-fp64 build.
//  - 4 rows / 256-thread block, thread t = float4 index t of each row:
//    every LDG/STG per-instruction fully coalesced.
//  - byte-packed codes, dp4a partials, packed-pair REDUX (16-bit halves,
//    32-lane sums <= 16256, no carry), 4x32-bit smem atomics.
//  - exp table u8[256] (gather conflict deg <= 2); ocode u8[128] = 32
//    words, one/bank -> conflict-FREE gather; .cs hints; lb(256,6).
// ---------------------------------------------------------------------------

// clamp(round-half-even(f), -128, 127) & 255 in one convert + one mask
__device__ __forceinline__ unsigned qhs_code(float f) {
    int r;
    asm("cvt.rni.sat.s8.f32 %0, %1;" : "=r"(r) : "f"(f));
    return (unsigned)r & 255u;
}

#define ROWS_PER_BLOCK 4

__global__ __launch_bounds__(256, 6) void qhs_main_kernel(
    const float4* __restrict__ x, float4* __restrict__ out,
    const float* __restrict__ scale_ptr)
{
    __shared__ unsigned char sk8[256];                    // exp codes (u8)
    __shared__ unsigned char ocode[ROWS_PER_BLOCK][128];  // out codes by k
    __shared__ int sS[ROWS_PER_BLOCK];                    // row sums

    const int tid = threadIdx.x;

    if (tid < ROWS_PER_BLOCK) sS[tid] = 0;

    // Kick off the 4 DRAM loads FIRST so the table build hides under them.
    const long long base =
        (long long)blockIdx.x * (ROWS_PER_BLOCK * 256) + tid;

    float4 v0 = __ldcs(&x[base]);
    float4 v1 = __ldcs(&x[base + 256]);
    float4 v2 = __ldcs(&x[base + 512]);
    float4 v3 = __ldcs(&x[base + 768]);

    // ---- fused exp-table build (1 entry per thread, hidden under loads) --
    {
        float scale = __ldg(scale_ptr);            // L2-resident broadcast
        int sv = (tid >= 128) ? (tid - 256) : tid; // two's-complement decode
        float val = (float)sv * 0.0625f * scale;   // fp32, matches reference
        float scaled = expf(val) * 128.0f;         // exact pow2 scaling
        float near = scaled - floorf(scaled);
        float dist = fabsf(near - 0.5f);           // to the rne boundary
        float r;
        if (dist < 1e-3f) {                        // rare exact tie-break
            r = (float)rint(exp((double)val) * 128.0);
        } else {
            r = rintf(scaled);                     // fp32 verdict is safe
        }
        r = fminf(fmaxf(r, 0.0f), 127.0f);
        sk8[tid] = (unsigned char)(int)r;
    }

    // Quantize to packed 8-bit codes (independent of tables) — uses the
    // loaded values, naturally ordered after the loads complete.
    unsigned pidx[4];
#define QHS_PACK(j, v)                                                  \
    pidx[j] = qhs_code(v.x * 16.0f)          |                          \
              (qhs_code(v.y * 16.0f) << 8)   |                          \
              (qhs_code(v.z * 16.0f) << 16)  |                          \
              (qhs_code(v.w * 16.0f) << 24)
    QHS_PACK(0, v0); QHS_PACK(1, v1); QHS_PACK(2, v2); QHS_PACK(3, v3);
#undef QHS_PACK

    __syncthreads();   // sk8 + sS ready

    // ---- Phase 1: gather k bytes, pack, packed-pair redux ---------------
    unsigned pk[4];
    unsigned d[4];
#pragma unroll
    for (int j = 0; j < 4; j++) {
        unsigned p = pidx[j];
        unsigned k0 = sk8[p & 255u];
        unsigned k1 = sk8[(p >> 8) & 255u];
        unsigned k2 = sk8[(p >> 16) & 255u];
        unsigned k3 = sk8[p >> 24];
        pk[j] = k0 | (k1 << 8) | (k2 << 16) | (k3 << 24);
        d[j] = __dp4a(pk[j], 0x01010101u, 0u);     // <= 508
    }
    // rows (0,1) and (2,3) in 16-bit halves; 32-lane sum <= 16256 (no carry)
    unsigned s01 = __reduce_add_sync(0xFFFFFFFFu, d[0] | (d[1] << 16));
    unsigned s23 = __reduce_add_sync(0xFFFFFFFFu, d[2] | (d[3] << 16));
    if ((tid & 31) == 0) {
        atomicAdd(&sS[0], (int)(s01 & 0xFFFFu));
        atomicAdd(&sS[1], (int)(s01 >> 16));
        atomicAdd(&sS[2], (int)(s23 & 0xFFFFu));
        atomicAdd(&sS[3], (int)(s23 >> 16));
    }

    __syncthreads();   // all sums complete

    // ---- Phase 2: per-row output-code tables (indexed by k) -------------
    // 4 rows x 128 entries = 512; each thread builds 2.
#pragma unroll
    for (int e = tid; e < ROWS_PER_BLOCK * 128; e += 256) {
        int rw = e >> 7;
        int kk = e & 127;
        float Sf = (float)sS[rw];                      // exact (< 2^18)
        // floor(S/k): IEEE div then floor — exact (err < 1/k fractional gap).
        // kk==0 -> +inf -> clipped to 1023 (reference e==0 branch).
        float t = fminf(floorf(__fdiv_rn(Sf, (float)kk)), 1023.0f);
        // t==0 -> +inf -> clipped to 127 (reference 1/0 saturation).
        float code = fminf(rintf(__fdiv_rn(128.0f, t)), 127.0f);
        ocode[rw][kk] = (unsigned char)(int)code;
    }

    __syncthreads();   // tables ready

    // ---- Phase 3: conflict-free byte gathers + coalesced stores ---------
#pragma unroll
    for (int j = 0; j < 4; j++) {
        unsigned p = pk[j];
        float4 o;
        o.x = (float)ocode[j][p & 255u]         * 0.0078125f;
        o.y = (float)ocode[j][(p >> 8) & 255u]  * 0.0078125f;
        o.z = (float)ocode[j][(p >> 16) & 255u] * 0.0078125f;
        o.w = (float)ocode[j][p >> 24]          * 0.0078125f;
        __stcs(&out[base + j * 256], o);
    }
}

extern "C" void kernel_launch(void* const* d_in, const int* in_sizes, int n_in,
                              void* d_out, int out_size) {
    const float* x     = (const float*)d_in[0];   // [4,12,1024,1024] fp32
    const float* scale = (const float*)d_in[1];   // scalar fp32

    const int n_elems = in_sizes[0];
    const int n_rows  = n_elems >> 10;                   // rows of 1024
    const int n_blocks = n_rows / ROWS_PER_BLOCK;        // 12288

    qhs_main_kernel<<<n_blocks, 256>>>((const float4*)x, (float4*)d_out,
                                       scale);
}